// round 8
// baseline (speedup 1.0000x reference)
#include <cuda_runtime.h>
#include <cuda_bf16.h>
#include <math.h>
#include <stdint.h>

// ---------------------------------------------------------------------------
// Problem constants (B=2, H=W=64, C=256, nh=4, hd=64, k=7)
// ---------------------------------------------------------------------------
#define NTOK   8192
#define CDIM   256
#define GK     256
#define QKVN   768
#define FFN    512
#define KS     7
#define KK     49

// ---------------------------------------------------------------------------
// Scratch (__device__ globals; allocation forbidden)
// ---------------------------------------------------------------------------
__device__ __nv_bfloat16 g_h   [NTOK * CDIM];
__device__ __nv_bfloat16 g_qkv [NTOK * QKVN];
__device__ __nv_bfloat16 g_attn[NTOK * CDIM];
__device__ float         g_x1  [NTOK * CDIM];
__device__ __nv_bfloat16 g_n2  [NTOK * CDIM];
__device__ __nv_bfloat16 g_ffh [NTOK * FFN];    // bf16
__device__ __nv_bfloat16 g_g   [NTOK * CDIM];
__device__ __nv_bfloat16 g_wqkvT[QKVN * GK];
__device__ __nv_bfloat16 g_wprojT[CDIM * GK];
__device__ __nv_bfloat16 g_ff1T [FFN  * GK];
__device__ __nv_bfloat16 g_ff2T [CDIM * GK];

// ---------------------------------------------------------------------------
// PTX helpers
// ---------------------------------------------------------------------------
__device__ __forceinline__ uint32_t smem_u32(const void* p) {
    uint32_t a;
    asm("{ .reg .u64 t; cvta.to.shared.u64 t, %1; cvt.u32.u64 %0, t; }"
        : "=r"(a) : "l"(p));
    return a;
}
#define LDMATRIX_X4(r0, r1, r2, r3, a) \
    asm volatile("ldmatrix.sync.aligned.m8n8.x4.shared.b16 {%0,%1,%2,%3}, [%4];" \
                 : "=r"(r0), "=r"(r1), "=r"(r2), "=r"(r3) : "r"(a))
#define LDMATRIX_X4_TRANS(r0, r1, r2, r3, a) \
    asm volatile("ldmatrix.sync.aligned.m8n8.x4.trans.shared.b16 {%0,%1,%2,%3}, [%4];" \
                 : "=r"(r0), "=r"(r1), "=r"(r2), "=r"(r3) : "r"(a))
#define MMA_BF16(d, a, b) \
    asm volatile("mma.sync.aligned.m16n8k16.row.col.f32.bf16.bf16.f32 " \
                 "{%0,%1,%2,%3}, {%4,%5,%6,%7}, {%8,%9}, {%0,%1,%2,%3};" \
                 : "+f"((d)[0]), "+f"((d)[1]), "+f"((d)[2]), "+f"((d)[3]) \
                 : "r"((a)[0]), "r"((a)[1]), "r"((a)[2]), "r"((a)[3]), \
                   "r"((b)[0]), "r"((b)[1]))
#define CP_ASYNC16(dst, src) \
    asm volatile("cp.async.cg.shared.global [%0], [%1], 16;" :: "r"(dst), "l"(src))
#define CP_COMMIT() asm volatile("cp.async.commit_group;" ::: "memory")
#define CP_WAIT(n)  asm volatile("cp.async.wait_group %0;" :: "n"(n) : "memory")

__device__ __forceinline__ uint32_t swz(uint32_t off) { return off ^ ((off >> 3) & 0x70); }
__device__ __forceinline__ uint32_t packbf(float a, float b) {
    __nv_bfloat162 h = __floats2bfloat162_rn(a, b);
    return *reinterpret_cast<uint32_t*>(&h);
}

// ---------------------------------------------------------------------------
// Fused weight convert+transpose (one launch for all 4 weights)
// ---------------------------------------------------------------------------
__global__ void transpose_all_kernel(const float* __restrict__ w0, __nv_bfloat16* __restrict__ o0,
                                     const float* __restrict__ w1, __nv_bfloat16* __restrict__ o1,
                                     const float* __restrict__ w2, __nv_bfloat16* __restrict__ o2,
                                     const float* __restrict__ w3, __nv_bfloat16* __restrict__ o3)
{
    const float* w; __nv_bfloat16* o; int N, nb;
    const int bx = blockIdx.x;
    if      (bx < 24) { w = w0; o = o0; N = QKVN; nb = bx;      }
    else if (bx < 32) { w = w1; o = o1; N = CDIM; nb = bx - 24; }
    else if (bx < 48) { w = w2; o = o2; N = FFN;  nb = bx - 32; }
    else              { w = w3; o = o3; N = CDIM; nb = bx - 48; }

    __shared__ float t[32][33];
    const int n0 = nb * 32, k0 = blockIdx.y * 32;
    const int tx = threadIdx.x, ty = threadIdx.y;
    #pragma unroll
    for (int i = 0; i < 32; i += 8)
        t[ty + i][tx] = w[(size_t)(k0 + ty + i) * N + n0 + tx];
    __syncthreads();
    #pragma unroll
    for (int i = 0; i < 32; i += 8)
        o[(size_t)(n0 + ty + i) * GK + k0 + tx] = __float2bfloat16(t[tx][ty + i]);
}

// ---------------------------------------------------------------------------
// RMSNorm (+ optional RoPE2D), fp32 in, bf16 out.
// ---------------------------------------------------------------------------
__global__ void rmsnorm_rope_kernel(const float* __restrict__ x,
                                    const float* __restrict__ w,
                                    __nv_bfloat16* __restrict__ out,
                                    int do_rope)
{
    const int t = blockIdx.x;
    const int i = threadIdx.x;
    float2 v = reinterpret_cast<const float2*>(x + (size_t)t * CDIM)[i];

    float ss = v.x * v.x + v.y * v.y;
    #pragma unroll
    for (int off = 16; off; off >>= 1)
        ss += __shfl_xor_sync(0xffffffffu, ss, off);
    __shared__ float red[4];
    if ((i & 31) == 0) red[i >> 5] = ss;
    __syncthreads();
    const float r = rsqrtf((red[0] + red[1] + red[2] + red[3]) * (1.0f / CDIM) + 1e-6f);

    const float2 wv = reinterpret_cast<const float2*>(w)[i];
    float a = v.x * r * wv.x;
    float b = v.y * r * wv.y;

    if (do_rope) {
        const int yy = (t >> 6) & 63;
        const int xx = t & 63;
        const int j  = i & 63;
        const float pos = (i < 64) ? (float)yy : (float)xx;
        const float inv = exp2f((float)j * (-13.28771237954945f / 64.0f));
        float c, s;
        sincosf(pos * inv, &s, &c);
        const float na = a * c - b * s;
        const float nb = a * s + b * c;
        a = na; b = nb;
    }
    reinterpret_cast<__nv_bfloat162*>(out + (size_t)t * CDIM)[i] =
        __floats2bfloat162_rn(a, b);
}

// ---------------------------------------------------------------------------
// mma.sync bf16 GEMM, double-buffered K-chunk ring, templated tile width.
// BN=128: 8 warps 2Mx4N (warp 64x32); BN=64: 8 warps 4Mx2N (warp 32x32).
// mode: 0 = bf16 out, 1 = fp32 +bias, 2 = fp32 +bias+residual, 3 = bf16 +bias
// ---------------------------------------------------------------------------
template<int BN>
__global__ __launch_bounds__(256, 2)
void gemm_mma_kernel(const __nv_bfloat16* __restrict__ A,
                     const __nv_bfloat16* __restrict__ Bt,
                     const float* __restrict__ bias,
                     const float* __restrict__ residual,
                     float* __restrict__ C,
                     __nv_bfloat16* __restrict__ Cb,
                     int N, int mode)
{
    constexpr int WM = (BN == 128) ? 2 : 4;          // warps in M
    constexpr int MT = (BN == 128) ? 4 : 2;          // m16 tiles per warp
    constexpr int BITERS = BN * 8 / 256;             // B loader iterations
    constexpr uint32_t STG = 16384u + (uint32_t)BN * 128u;   // stage stride

    extern __shared__ __align__(1024) char smem[];
    const uint32_t sb = smem_u32(smem);
    const int tid  = threadIdx.x;
    const int wid  = tid >> 5;
    const int lane = tid & 31;
    const int bm   = blockIdx.y * 128;
    const int bn   = blockIdx.x * BN;
    const int wm   = wid % WM;
    const int wn   = wid / WM;

    const int lrow = tid >> 3;
    const int lch  = tid & 7;

    #define LOAD_CHUNK(kc, stage) do {                                           \
        const uint32_t s0 = (uint32_t)(stage) * STG;                             \
        _Pragma("unroll")                                                        \
        for (int it = 0; it < 4; it++) {                                         \
            const int row = it * 32 + lrow;                                      \
            uint32_t off = swz((uint32_t)row * 128u + (uint32_t)lch * 16u);      \
            CP_ASYNC16(sb + s0 + off,                                            \
                       A + (size_t)(bm + row) * GK + (kc) * 64 + lch * 8);       \
        }                                                                        \
        _Pragma("unroll")                                                        \
        for (int it = 0; it < BITERS; it++) {                                    \
            const int row = it * 32 + lrow;                                      \
            uint32_t off = swz((uint32_t)row * 128u + (uint32_t)lch * 16u);      \
            CP_ASYNC16(sb + s0 + 16384u + off,                                   \
                       Bt + (size_t)(bn + row) * GK + (kc) * 64 + lch * 8);      \
        }                                                                        \
        CP_COMMIT();                                                             \
    } while (0)

    LOAD_CHUNK(0, 0);
    LOAD_CHUNK(1, 1);

    float acc[MT][4][4] = {};
    const int mtx = lane >> 3;
    const int l7  = lane & 7;

    #pragma unroll
    for (int kc = 0; kc < 4; kc++) {
        if (kc < 3) CP_WAIT(1); else CP_WAIT(0);
        __syncthreads();

        const uint32_t sA = sb + (uint32_t)(kc & 1) * STG;
        const uint32_t sB = sA + 16384u;

        #pragma unroll
        for (int s16 = 0; s16 < 4; s16++) {
            const int chunk0 = s16 * 2;

            uint32_t af[MT][4];
            #pragma unroll
            for (int mt = 0; mt < MT; mt++) {
                const int row   = wm * (MT * 16) + mt * 16 + (mtx & 1) * 8 + l7;
                const int chunk = chunk0 + (mtx >> 1);
                LDMATRIX_X4(af[mt][0], af[mt][1], af[mt][2], af[mt][3],
                            sA + swz((uint32_t)row * 128u + (uint32_t)chunk * 16u));
            }
            uint32_t bf[4][2];
            #pragma unroll
            for (int pair = 0; pair < 2; pair++) {
                const int nrow  = wn * 32 + pair * 16 + (mtx >> 1) * 8 + l7;
                const int chunk = chunk0 + (mtx & 1);
                LDMATRIX_X4(bf[pair * 2][0], bf[pair * 2][1],
                            bf[pair * 2 + 1][0], bf[pair * 2 + 1][1],
                            sB + swz((uint32_t)nrow * 128u + (uint32_t)chunk * 16u));
            }
            #pragma unroll
            for (int mt = 0; mt < MT; mt++)
                #pragma unroll
                for (int nt = 0; nt < 4; nt++)
                    MMA_BF16(acc[mt][nt], af[mt], bf[nt]);
        }
        __syncthreads();
        if (kc < 2) LOAD_CHUNK(kc + 2, kc & 1);
    }
    #undef LOAD_CHUNK

    const int rbase = bm + wm * (MT * 16) + (lane >> 2);
    const int cbase = bn + wn * 32 + (lane & 3) * 2;
    #pragma unroll
    for (int mt = 0; mt < MT; mt++) {
        #pragma unroll
        for (int half = 0; half < 2; half++) {
            const int row = rbase + mt * 16 + half * 8;
            #pragma unroll
            for (int nt = 0; nt < 4; nt++) {
                const int col = cbase + nt * 8;
                float ox = acc[mt][nt][half * 2];
                float oy = acc[mt][nt][half * 2 + 1];
                const size_t idx = (size_t)row * N + col;
                if (mode == 0) {
                    *reinterpret_cast<__nv_bfloat162*>(&Cb[idx]) =
                        __floats2bfloat162_rn(ox, oy);
                } else {
                    ox += bias[col];
                    oy += bias[col + 1];
                    if (mode == 2) {
                        const float2 rr = *reinterpret_cast<const float2*>(&residual[idx]);
                        ox += rr.x; oy += rr.y;
                        *reinterpret_cast<float2*>(&C[idx]) = make_float2(ox, oy);
                    } else if (mode == 3) {
                        *reinterpret_cast<__nv_bfloat162*>(&Cb[idx]) =
                            __floats2bfloat162_rn(ox, oy);
                    } else {
                        *reinterpret_cast<float2*>(&C[idx]) = make_float2(ox, oy);
                    }
                }
            }
        }
    }
}

// ---------------------------------------------------------------------------
// Tiled tensor-core neighborhood attention, register-resident P.
// 8 warps: wm 0..3 (16 rows), wn 0..1 (112 kv half). Phase 2 contracts each
// warp's kv half from registers; partial O reduced via smem (reuses K region).
// ---------------------------------------------------------------------------
#define AT_Q    0
#define AT_K    8192
#define AT_V    36864
#define AT_RED  8192              // overlays K (dead after phase 1)
#define AT_MAX  65536
#define AT_SUM  66048
#define AT_SIZE 66560
#define REDW    68                // padded fp32 row stride

__global__ __launch_bounds__(256, 2)
void attn_mma_kernel(const __nv_bfloat16* __restrict__ qkv,
                     __nv_bfloat16* __restrict__ out)
{
    extern __shared__ __align__(1024) char smem[];
    const uint32_t sb = smem_u32(smem);
    float* smax = reinterpret_cast<float*>(smem + AT_MAX);
    float* ssum = reinterpret_cast<float*>(smem + AT_SUM);
    float* sred = reinterpret_cast<float*>(smem + AT_RED);

    const int tid  = threadIdx.x;
    const int wid  = tid >> 5;
    const int lane = tid & 31;
    const int head = blockIdx.y;
    const int b    = blockIdx.z;
    const int ty0  = (blockIdx.x >> 3) * 8;
    const int tx0  = (blockIdx.x & 7) * 8;
    const int ny0  = min(max(ty0 - 3, 0), 50);
    const int nx0  = min(max(tx0 - 3, 0), 50);

    const __nv_bfloat16* base = qkv + (size_t)b * 4096 * QKVN + head * 64;

    // ---- async loads: Q, K, V ----
    #pragma unroll
    for (int i = 0; i < 2; i++) {
        const int idx = i * 256 + tid;
        const int m = idx >> 3, ch = idx & 7;
        const int y = ty0 + (m >> 3), x = tx0 + (m & 7);
        uint32_t off = swz((uint32_t)m * 128u + (uint32_t)ch * 16u);
        CP_ASYNC16(sb + AT_Q + off, base + (size_t)(y * 64 + x) * QKVN + ch * 8);
    }
    CP_COMMIT();
    #pragma unroll
    for (int i = 0; i < 7; i++) {
        const int idx = i * 256 + tid;
        const int kv = idx >> 3, ch = idx & 7;
        const int r = kv >> 4, c = kv & 15;
        uint32_t off = swz((uint32_t)kv * 128u + (uint32_t)ch * 16u);
        if (c < 14)
            CP_ASYNC16(sb + AT_K + off,
                       base + (size_t)((ny0 + r) * 64 + nx0 + c) * QKVN + CDIM + ch * 8);
        else
            *reinterpret_cast<uint4*>(smem + AT_K + off) = make_uint4(0, 0, 0, 0);
    }
    CP_COMMIT();
    #pragma unroll
    for (int i = 0; i < 7; i++) {
        const int idx = i * 256 + tid;
        const int kv = idx >> 3, ch = idx & 7;
        const int r = kv >> 4, c = kv & 15;
        uint32_t off = swz((uint32_t)kv * 128u + (uint32_t)ch * 16u);
        if (c < 14)
            CP_ASYNC16(sb + AT_V + off,
                       base + (size_t)((ny0 + r) * 64 + nx0 + c) * QKVN + 2 * CDIM + ch * 8);
        else
            *reinterpret_cast<uint4*>(smem + AT_V + off) = make_uint4(0, 0, 0, 0);
    }
    CP_COMMIT();

    const int wm  = wid & 3;
    const int wn  = wid >> 2;
    const int mtx = lane >> 3;
    const int l7  = lane & 7;

    CP_WAIT(1);
    __syncthreads();

    // ---- phase 1: S = Q @ K^T ----
    uint32_t af[4][4];
    #pragma unroll
    for (int k16 = 0; k16 < 4; k16++) {
        const int row   = wm * 16 + (mtx & 1) * 8 + l7;
        const int chunk = k16 * 2 + (mtx >> 1);
        LDMATRIX_X4(af[k16][0], af[k16][1], af[k16][2], af[k16][3],
                    sb + AT_Q + swz((uint32_t)row * 128u + (uint32_t)chunk * 16u));
    }

    float acc[14][4] = {};
    #pragma unroll
    for (int k16 = 0; k16 < 4; k16++) {
        #pragma unroll
        for (int grp = 0; grp < 2; grp++) {
            const int nt0    = grp * 8;
            const int npairs = grp ? 3 : 4;
            uint32_t bf[8][2];
            #pragma unroll
            for (int pair = 0; pair < 4; pair++) {
                if (pair < npairs) {
                    const int nrow  = wn * 112 + (nt0 + pair * 2) * 8 + (mtx >> 1) * 8 + l7;
                    const int chunk = k16 * 2 + (mtx & 1);
                    LDMATRIX_X4(bf[pair * 2][0], bf[pair * 2][1],
                                bf[pair * 2 + 1][0], bf[pair * 2 + 1][1],
                                sb + AT_K + swz((uint32_t)nrow * 128u + (uint32_t)chunk * 16u));
                }
            }
            const int ntiles = grp ? 6 : 8;
            #pragma unroll
            for (int j = 0; j < 8; j++)
                if (j < ntiles)
                    MMA_BF16(acc[nt0 + j], af[k16], bf[j]);
        }
    }

    // ---- masks ----
    const int row0 = wm * 16 + (lane >> 2);
    const int row1 = row0 + 8;
    const int y_a = ty0 + (row0 >> 3), x_a = tx0 + (row0 & 7);
    const int y_b = ty0 + (row1 >> 3), x_b = tx0 + (row1 & 7);
    const int rlo_a = min(max(y_a - 3, 0), 57) - ny0;
    const int clo_a = min(max(x_a - 3, 0), 57) - nx0;
    const int rlo_b = min(max(y_b - 3, 0), 57) - ny0;
    const int clo_b = min(max(x_b - 3, 0), 57) - nx0;

    uint32_t vm_a = 0, vm_b = 0;
    #pragma unroll
    for (int nt = 0; nt < 14; nt++) {
        #pragma unroll
        for (int j = 0; j < 2; j++) {
            const int n = wn * 112 + nt * 8 + (lane & 3) * 2 + j;
            const int r = n >> 4, c = n & 15;
            if (c < 14 && (unsigned)(r - rlo_a) < 7u && (unsigned)(c - clo_a) < 7u)
                vm_a |= 1u << (nt * 2 + j);
            if (c < 14 && (unsigned)(r - rlo_b) < 7u && (unsigned)(c - clo_b) < 7u)
                vm_b |= 1u << (nt * 2 + j);
        }
    }

    // ---- row max ----
    float mx_a = -3e38f, mx_b = -3e38f;
    #pragma unroll
    for (int nt = 0; nt < 14; nt++) {
        #pragma unroll
        for (int j = 0; j < 2; j++) {
            if (vm_a & (1u << (nt * 2 + j))) mx_a = fmaxf(mx_a, acc[nt][j]);
            if (vm_b & (1u << (nt * 2 + j))) mx_b = fmaxf(mx_b, acc[nt][2 + j]);
        }
    }
    mx_a = fmaxf(mx_a, __shfl_xor_sync(0xffffffffu, mx_a, 1));
    mx_a = fmaxf(mx_a, __shfl_xor_sync(0xffffffffu, mx_a, 2));
    mx_b = fmaxf(mx_b, __shfl_xor_sync(0xffffffffu, mx_b, 1));
    mx_b = fmaxf(mx_b, __shfl_xor_sync(0xffffffffu, mx_b, 2));
    if ((lane & 3) == 0) {
        smax[row0 * 2 + wn] = mx_a;
        smax[row1 * 2 + wn] = mx_b;
    }
    __syncthreads();
    const float M_a = fmaxf(smax[row0 * 2], smax[row0 * 2 + 1]);
    const float M_b = fmaxf(smax[row1 * 2], smax[row1 * 2 + 1]);

    // ---- exp + row sum ----
    const float SC = 0.18033688011112042f;   // 0.125 * log2(e)
    float sm_a = 0.0f, sm_b = 0.0f;
    #pragma unroll
    for (int nt = 0; nt < 14; nt++) {
        #pragma unroll
        for (int j = 0; j < 2; j++) {
            float ea = (vm_a & (1u << (nt * 2 + j)))
                     ? exp2f((acc[nt][j] - M_a) * SC) : 0.0f;
            float eb = (vm_b & (1u << (nt * 2 + j)))
                     ? exp2f((acc[nt][2 + j] - M_b) * SC) : 0.0f;
            acc[nt][j] = ea; acc[nt][2 + j] = eb;
            sm_a += ea; sm_b += eb;
        }
    }
    sm_a += __shfl_xor_sync(0xffffffffu, sm_a, 1);
    sm_a += __shfl_xor_sync(0xffffffffu, sm_a, 2);
    sm_b += __shfl_xor_sync(0xffffffffu, sm_b, 1);
    sm_b += __shfl_xor_sync(0xffffffffu, sm_b, 2);
    if ((lane & 3) == 0) {
        ssum[row0 * 2 + wn] = sm_a;
        ssum[row1 * 2 + wn] = sm_b;
    }

    // ---- pack P fragments from registers (A-frag layout) ----
    uint32_t pf[7][4];
    #pragma unroll
    for (int s = 0; s < 7; s++) {
        pf[s][0] = packbf(acc[2 * s][0],     acc[2 * s][1]);
        pf[s][1] = packbf(acc[2 * s][2],     acc[2 * s][3]);
        pf[s][2] = packbf(acc[2 * s + 1][0], acc[2 * s + 1][1]);
        pf[s][3] = packbf(acc[2 * s + 1][2], acc[2 * s + 1][3]);
    }

    CP_WAIT(0);
    __syncthreads();     // V ready; all K reads done (red overlays K)

    // ---- phase 2: partial O = P_half @ V_half (per warp kv half) ----
    float accO[8][4] = {};
    #pragma unroll
    for (int s = 0; s < 7; s++) {
        uint32_t vf[8][2];
        #pragma unroll
        for (int g2 = 0; g2 < 4; g2++) {
            const int kvrow = (wn * 7 + s) * 16 + (lane & 15);
            const int colb  = (g2 * 16 + (lane >> 4) * 8) * 2;
            LDMATRIX_X4_TRANS(vf[g2 * 2][0], vf[g2 * 2][1],
                              vf[g2 * 2 + 1][0], vf[g2 * 2 + 1][1],
                              sb + AT_V + swz((uint32_t)kvrow * 128u + (uint32_t)colb));
        }
        #pragma unroll
        for (int nt = 0; nt < 8; nt++)
            MMA_BF16(accO[nt], pf[s], vf[nt]);
    }

    // ---- cross-warp reduce (wn=1 -> smem, wn=0 adds) ----
    if (wn == 1) {
        #pragma unroll
        for (int nt = 0; nt < 8; nt++) {
            const int col = nt * 8 + (lane & 3) * 2;
            *reinterpret_cast<float2*>(&sred[row0 * REDW + col]) =
                make_float2(accO[nt][0], accO[nt][1]);
            *reinterpret_cast<float2*>(&sred[row1 * REDW + col]) =
                make_float2(accO[nt][2], accO[nt][3]);
        }
    }
    __syncthreads();

    if (wn == 0) {
        const float inv_a = 1.0f / (ssum[row0 * 2] + ssum[row0 * 2 + 1]);
        const float inv_b = 1.0f / (ssum[row1 * 2] + ssum[row1 * 2 + 1]);
        const size_t t_a = (size_t)b * 4096 + (size_t)(y_a * 64 + x_a);
        const size_t t_b = (size_t)b * 4096 + (size_t)(y_b * 64 + x_b);
        #pragma unroll
        for (int nt = 0; nt < 8; nt++) {
            const int col = nt * 8 + (lane & 3) * 2;
            const float2 ra = *reinterpret_cast<const float2*>(&sred[row0 * REDW + col]);
            const float2 rb = *reinterpret_cast<const float2*>(&sred[row1 * REDW + col]);
            *reinterpret_cast<__nv_bfloat162*>(out + t_a * CDIM + head * 64 + col) =
                __floats2bfloat162_rn((accO[nt][0] + ra.x) * inv_a,
                                      (accO[nt][1] + ra.y) * inv_a);
            *reinterpret_cast<__nv_bfloat162*>(out + t_b * CDIM + head * 64 + col) =
                __floats2bfloat162_rn((accO[nt][2] + rb.x) * inv_b,
                                      (accO[nt][3] + rb.y) * inv_b);
        }
    }
}

// ---------------------------------------------------------------------------
// GeGLU: g = gelu_exact(gate) * value   (bf16 in, bf16 out)
// ---------------------------------------------------------------------------
__global__ void geglu_kernel(const __nv_bfloat16* __restrict__ ffh,
                             __nv_bfloat16* __restrict__ g)
{
    const int idx = blockIdx.x * blockDim.x + threadIdx.x;
    const int row = idx >> 8;
    const int col = idx & 255;
    const float gate = __bfloat162float(ffh[(size_t)row * FFN + col]);
    const float val  = __bfloat162float(ffh[(size_t)row * FFN + CDIM + col]);
    const float ge = 0.5f * gate * (1.0f + erff(gate * 0.70710678118654752f));
    g[idx] = __float2bfloat16(ge * val);
}

// ---------------------------------------------------------------------------
// Launch
// ---------------------------------------------------------------------------
#define SM_SIZE128 65536
#define SM_SIZE64  49152

extern "C" void kernel_launch(void* const* d_in, const int* in_sizes, int n_in,
                              void* d_out, int out_size)
{
    const float* x       = (const float*)d_in[0];
    const float* norm1_w = (const float*)d_in[1];
    const float* norm2_w = (const float*)d_in[2];
    const float* w_qkv   = (const float*)d_in[3];
    const float* w_proj  = (const float*)d_in[4];
    const float* b_proj  = (const float*)d_in[5];
    const float* ff1_w   = (const float*)d_in[6];
    const float* ff1_b   = (const float*)d_in[7];
    const float* ff2_w   = (const float*)d_in[8];
    const float* ff2_b   = (const float*)d_in[9];
    float* out = (float*)d_out;

    __nv_bfloat16 *p_h, *p_qkv, *p_attn, *p_n2, *p_g, *p_ffh;
    __nv_bfloat16 *p_wqkvT, *p_wprojT, *p_ff1T, *p_ff2T;
    float *p_x1;
    cudaGetSymbolAddress((void**)&p_h,      g_h);
    cudaGetSymbolAddress((void**)&p_qkv,    g_qkv);
    cudaGetSymbolAddress((void**)&p_attn,   g_attn);
    cudaGetSymbolAddress((void**)&p_x1,     g_x1);
    cudaGetSymbolAddress((void**)&p_n2,     g_n2);
    cudaGetSymbolAddress((void**)&p_ffh,    g_ffh);
    cudaGetSymbolAddress((void**)&p_g,      g_g);
    cudaGetSymbolAddress((void**)&p_wqkvT,  g_wqkvT);
    cudaGetSymbolAddress((void**)&p_wprojT, g_wprojT);
    cudaGetSymbolAddress((void**)&p_ff1T,   g_ff1T);
    cudaGetSymbolAddress((void**)&p_ff2T,   g_ff2T);

    cudaFuncSetAttribute(gemm_mma_kernel<128>,
                         cudaFuncAttributeMaxDynamicSharedMemorySize, SM_SIZE128);
    cudaFuncSetAttribute(gemm_mma_kernel<64>,
                         cudaFuncAttributeMaxDynamicSharedMemorySize, SM_SIZE64);
    cudaFuncSetAttribute(attn_mma_kernel,
                         cudaFuncAttributeMaxDynamicSharedMemorySize, AT_SIZE);

    // 0. all weight transposes in one launch
    transpose_all_kernel<<<dim3(56, 8), dim3(32, 8)>>>(
        w_qkv, p_wqkvT, w_proj, p_wprojT, ff1_w, p_ff1T, ff2_w, p_ff2T);

    // 1. h = rope2d(rmsnorm(x)) -> bf16
    rmsnorm_rope_kernel<<<NTOK, 128>>>(x, norm1_w, p_h, 1);

    // 2. qkv = h @ w_qkv -> bf16
    gemm_mma_kernel<128><<<dim3(QKVN / 128, NTOK / 128), 256, SM_SIZE128>>>(
        p_h, p_wqkvT, nullptr, nullptr, nullptr, p_qkv, QKVN, 0);

    // 3. attention -> bf16
    attn_mma_kernel<<<dim3(64, 4, 2), 256, AT_SIZE>>>(p_qkv, p_attn);

    // 4. x1 = x + attn @ w_proj + b_proj   (fp32, BN=64 -> 256 CTAs)
    gemm_mma_kernel<64><<<dim3(CDIM / 64, NTOK / 128), 256, SM_SIZE64>>>(
        p_attn, p_wprojT, b_proj, x, p_x1, nullptr, CDIM, 2);

    // 5. n2 = rmsnorm(x1) -> bf16
    rmsnorm_rope_kernel<<<NTOK, 128>>>(p_x1, norm2_w, p_n2, 0);

    // 6. ffh = n2 @ ff1_w + ff1_b -> bf16
    gemm_mma_kernel<128><<<dim3(FFN / 128, NTOK / 128), 256, SM_SIZE128>>>(
        p_n2, p_ff1T, ff1_b, nullptr, nullptr, p_ffh, FFN, 3);

    // 7. g = gelu(gate) * value -> bf16
    geglu_kernel<<<(NTOK * CDIM) / 256, 256>>>(p_ffh, p_g);

    // 8. out = x1 + g @ ff2_w + ff2_b   (fp32, BN=64)
    gemm_mma_kernel<64><<<dim3(CDIM / 64, NTOK / 128), 256, SM_SIZE64>>>(
        p_g, p_ff2T, ff2_b, p_x1, out, nullptr, CDIM, 2);
}